// round 14
// baseline (speedup 1.0000x reference)
#include <cuda_runtime.h>
#include <cuda_bf16.h>
#include <cstdint>
#include <math.h>

#define N_DST 50000
#define L_MAX 16
#define D 256
#define N_CLS 104

// ---------------------------------------------------------------------------
// Scratch (allocation-free rule: __device__ globals)
// ---------------------------------------------------------------------------
__device__ __align__(16) float g_last[(size_t)N_DST * D];
__device__ __align__(16) float g_h0[(size_t)N_DST * D];
__device__ __align__(16) float g_h1[(size_t)N_DST * D];
// int8 two-digit quantized GEMM operands (A side)
__device__ __align__(16) int8_t g_last_q1[(size_t)N_DST * D];
__device__ __align__(16) int8_t g_last_q2[(size_t)N_DST * D];
__device__ __align__(16) int8_t g_h0_q1[(size_t)N_DST * D];
__device__ __align__(16) int8_t g_h0_q2[(size_t)N_DST * D];
__device__ float g_sl[N_DST];
__device__ float g_sh[N_DST];
// GRU weights, quantized+permuted: [c16(16)][kc(8)][digit(2)*96 rows][32]
// row within chunk: row = g8*48 + gate*8 + dd   (g8 0..1, gate 0..5, dd 0..7)
#define WGQ_TOTAL (16 * 8 * 192 * 32)
__device__ __align__(16) int8_t w_gru_q12[WGQ_TOTAL];
__device__ float w_sg[6 * 256];
// FC path stays bf16-split
__device__ __align__(16) __nv_bfloat16 g_ft_h[(size_t)N_DST * D];
__device__ __align__(16) __nv_bfloat16 g_ft_l[(size_t)N_DST * D];
#define WF_TOTAL (8 * 104 * 32)
__device__ __align__(16) __nv_bfloat16 w_fc_h[WF_TOTAL];
__device__ __align__(16) __nv_bfloat16 w_fc_l[WF_TOTAL];

// ---------------------------------------------------------------------------
// Helpers
// ---------------------------------------------------------------------------
__device__ __forceinline__ uint32_t smem_u32(const void* p) {
    uint32_t a;
    asm("{ .reg .u64 t; cvta.to.shared.u64 t, %1; cvt.u32.u64 %0, t; }"
        : "=r"(a) : "l"(p));
    return a;
}
__device__ __forceinline__ void ldsm4(uint32_t* r, uint32_t addr) {
    asm volatile("ldmatrix.sync.aligned.m8n8.x4.shared.b16 {%0,%1,%2,%3}, [%4];"
                 : "=r"(r[0]), "=r"(r[1]), "=r"(r[2]), "=r"(r[3]) : "r"(addr));
}
__device__ __forceinline__ void ldsm2(uint32_t* r, uint32_t addr) {
    asm volatile("ldmatrix.sync.aligned.m8n8.x2.shared.b16 {%0,%1}, [%2];"
                 : "=r"(r[0]), "=r"(r[1]) : "r"(addr));
}
__device__ __forceinline__ void mma16816(float* acc, const uint32_t* a, const uint32_t* b) {
    asm volatile("mma.sync.aligned.m16n8k16.row.col.f32.bf16.bf16.f32 "
                 "{%0,%1,%2,%3}, {%4,%5,%6,%7}, {%8,%9}, {%0,%1,%2,%3};"
                 : "+f"(acc[0]), "+f"(acc[1]), "+f"(acc[2]), "+f"(acc[3])
                 : "r"(a[0]), "r"(a[1]), "r"(a[2]), "r"(a[3]),
                   "r"(b[0]), "r"(b[1]));
}
__device__ __forceinline__ void imma16832(int* d, const uint32_t* a, const uint32_t* b) {
    asm volatile("mma.sync.aligned.m16n8k32.row.col.s32.s8.s8.s32 "
                 "{%0,%1,%2,%3}, {%4,%5,%6,%7}, {%8,%9}, {%0,%1,%2,%3};"
                 : "+r"(d[0]), "+r"(d[1]), "+r"(d[2]), "+r"(d[3])
                 : "r"(a[0]), "r"(a[1]), "r"(a[2]), "r"(a[3]),
                   "r"(b[0]), "r"(b[1]));
}
__device__ __forceinline__ uint32_t pack_bf16(float a, float b) {
    uint32_t r;
    asm("cvt.rn.bf16x2.f32 %0, %1, %2;" : "=r"(r) : "f"(b), "f"(a));
    return r;
}
__device__ __forceinline__ float lowf(uint32_t p) {
    __nv_bfloat162 v = *(__nv_bfloat162*)&p; return __bfloat162float(v.x);
}
__device__ __forceinline__ float highf(uint32_t p) {
    __nv_bfloat162 v = *(__nv_bfloat162*)&p; return __bfloat162float(v.y);
}
__device__ __forceinline__ void split4(float4 v, uint2& hi, uint2& lo) {
    uint32_t h0 = pack_bf16(v.x, v.y);
    uint32_t h1 = pack_bf16(v.z, v.w);
    uint32_t l0 = pack_bf16(v.x - lowf(h0), v.y - highf(h0));
    uint32_t l1 = pack_bf16(v.z - lowf(h1), v.w - highf(h1));
    hi = make_uint2(h0, h1);
    lo = make_uint2(l0, l1);
}
__device__ __forceinline__ void split_store8(__nv_bfloat16* ph, __nv_bfloat16* pl,
                                             float4 a, float4 b) {
    uint2 h0, l0, h1, l1;
    split4(a, h0, l0);
    split4(b, h1, l1);
    *(uint4*)ph = make_uint4(h0.x, h0.y, h1.x, h1.y);
    *(uint4*)pl = make_uint4(l0.x, l0.y, l1.x, l1.y);
}
__device__ __forceinline__ void cp16(uint32_t dst, const void* src) {
    asm volatile("cp.async.cg.shared.global [%0], [%1], 16;"
                 :: "r"(dst), "l"(src));
}
#define CP_COMMIT() asm volatile("cp.async.commit_group;" ::: "memory")
#define CP_WAIT(N)  asm volatile("cp.async.wait_group %0;" :: "n"(N) : "memory")

__device__ __forceinline__ float sigm(float x)   { return 1.f / (1.f + __expf(-x)); }
__device__ __forceinline__ float tanh_f(float x) { return 2.f / (1.f + __expf(-2.f * x)) - 1.f; }

// two-digit int8 quantization of 8 values; inv = 127/max, s1 = max/127
__device__ __forceinline__ void quant8(const float* v, float inv, float s1,
                                       uint2& o1, uint2& o2) {
    uint32_t w1[2] = {0, 0}, w2[2] = {0, 0};
    #pragma unroll
    for (int i = 0; i < 8; ++i) {
        float qf = fminf(fmaxf(rintf(v[i] * inv), -127.f), 127.f);
        float r  = v[i] - qf * s1;
        float q2f = fminf(fmaxf(rintf(r * inv * 128.f), -127.f), 127.f);
        int q1 = (int)qf, q2 = (int)q2f;
        w1[i >> 2] |= ((uint32_t)(q1 & 255)) << ((i & 3) * 8);
        w2[i >> 2] |= ((uint32_t)(q2 & 255)) << ((i & 3) * 8);
    }
    o1 = make_uint2(w1[0], w1[1]);
    o2 = make_uint2(w2[0], w2[1]);
}

// ---------------------------------------------------------------------------
// Kernel 0a: quantize + permute GRU weights. One warp per (c16, row).
// row = g8*48 + gate*8 + dd per 16-dim chunk.
// ---------------------------------------------------------------------------
__global__ void split_w_gru_q(const float* __restrict__ Wih,
                              const float* __restrict__ Whh)
{
    int wid = threadIdx.x >> 5, lane = threadIdx.x & 31;
    int w = blockIdx.x * 8 + wid;            // 0..1535
    int c = w / 96, row = w % 96;
    int g8 = row / 48, rem = row % 48;
    int gate = rem >> 3, dd = rem & 7;
    int dim = c * 16 + g8 * 8 + dd;
    const float* Wp = (gate < 3) ? Wih : Whh;
    int gg = (gate < 3) ? gate : gate - 3;
    const float* src = Wp + (size_t)(gg * 256 + dim) * D + lane * 8;

    float v[8]; float mx = 0.f;
    #pragma unroll
    for (int i = 0; i < 8; ++i) { v[i] = src[i]; mx = fmaxf(mx, fabsf(v[i])); }
    #pragma unroll
    for (int o = 16; o > 0; o >>= 1) mx = fmaxf(mx, __shfl_xor_sync(0xffffffffu, mx, o));
    mx = fmaxf(mx, 1e-20f);
    float s1 = mx * (1.f / 127.f), inv = 127.f / mx;

    uint2 o1, o2;
    quant8(v, inv, s1, o1, o2);
    int kc = lane >> 2, koff = (lane & 3) * 8;
    size_t base = ((size_t)(c * 8 + kc) * 192 + row) * 32 + koff;
    *(uint2*)&w_gru_q12[base]           = o1;   // digit 0 rows [0,96)
    *(uint2*)&w_gru_q12[base + 96 * 32] = o2;   // digit 1 rows [96,192)
    if (lane == 0) w_sg[gate * 256 + dim] = s1;
}

// ---------------------------------------------------------------------------
// Kernel 0b: split fc_w (bf16 hi/lo).
// ---------------------------------------------------------------------------
__global__ void split_w_fc_kernel(const float* __restrict__ fcw)
{
    int idx = blockIdx.x * 256 + threadIdx.x;
    if (idx >= WF_TOTAL) return;
    int k   = idx & 31;
    int r2  = idx >> 5;
    int row = r2 % 104;
    int kc  = r2 / 104;
    float v = fcw[(size_t)row * D + kc * 32 + k];
    __nv_bfloat16 h = __float2bfloat16_rn(v);
    w_fc_h[idx] = h;
    w_fc_l[idx] = __float2bfloat16_rn(v - __bfloat162float(h));
}

// ---------------------------------------------------------------------------
// Kernel 1: mailbox gather. One warp per node; emits fp32 + int8 quantized.
// ---------------------------------------------------------------------------
__global__ void gather_kernel(const int* __restrict__ tokens,
                              const int* __restrict__ degrees,
                              const float* __restrict__ emb)
{
    int gw   = (blockIdx.x * blockDim.x + threadIdx.x) >> 5;
    int lane = threadIdx.x & 31;
    if (gw >= N_DST) return;

    int deg = degrees[gw];
    deg = max(1, min(deg, L_MAX));

    const int* tk = tokens + gw * L_MAX;
    int mytok = (lane < L_MAX) ? tk[lane] : 0;

    int base = lane * 8;
    float4 a0 = make_float4(0.f, 0.f, 0.f, 0.f), a1 = a0;

    for (int l = 0; l < deg - 1; ++l) {
        int tkn = __shfl_sync(0xffffffffu, mytok, l);
        const float4* e = (const float4*)(emb + (size_t)tkn * D + base);
        float4 v0 = e[0], v1 = e[1];
        a0.x += v0.x; a0.y += v0.y; a0.z += v0.z; a0.w += v0.w;
        a1.x += v1.x; a1.y += v1.y; a1.z += v1.z; a1.w += v1.w;
    }
    int tl = __shfl_sync(0xffffffffu, mytok, deg - 1);
    const float4* e = (const float4*)(emb + (size_t)tl * D + base);
    float4 l0 = e[0], l1 = e[1];

    size_t o = (size_t)gw * D + base;
    *(float4*)&g_h0[o]       = a0;
    *(float4*)&g_h0[o + 4]   = a1;
    *(float4*)&g_last[o]     = l0;
    *(float4*)&g_last[o + 4] = l1;

    float vl[8] = {l0.x, l0.y, l0.z, l0.w, l1.x, l1.y, l1.z, l1.w};
    float vh[8] = {a0.x, a0.y, a0.z, a0.w, a1.x, a1.y, a1.z, a1.w};
    float ml = 0.f, mh = 0.f;
    #pragma unroll
    for (int i = 0; i < 8; ++i) {
        ml = fmaxf(ml, fabsf(vl[i]));
        mh = fmaxf(mh, fabsf(vh[i]));
    }
    #pragma unroll
    for (int of = 16; of > 0; of >>= 1) {
        ml = fmaxf(ml, __shfl_xor_sync(0xffffffffu, ml, of));
        mh = fmaxf(mh, __shfl_xor_sync(0xffffffffu, mh, of));
    }
    ml = fmaxf(ml, 1e-20f); mh = fmaxf(mh, 1e-20f);
    float s1l = ml * (1.f / 127.f), invl = 127.f / ml;
    float s1h = mh * (1.f / 127.f), invh = 127.f / mh;

    uint2 q1, q2;
    quant8(vl, invl, s1l, q1, q2);
    *(uint2*)&g_last_q1[o] = q1;
    *(uint2*)&g_last_q2[o] = q2;
    quant8(vh, invh, s1h, q1, q2);
    *(uint2*)&g_h0_q1[o] = q1;
    *(uint2*)&g_h0_q2[o] = q2;
    if (lane == 0) { g_sl[gw] = s1l; g_sh[gw] = s1h; }
}

// ---------------------------------------------------------------------------
// Kernel 2: PERSISTENT fused GRU, two-digit int8 IMMA, C tile 128 x 96.
// Grid = 148; CTA pinned to 16-dim chunk c. B resident (72 KB). A staged in
// HALF-TILE granularity (4 kc = 72 KB each), interleaved 144B-pitch rows
// (4 regions x 32B; 144 mod 128 = 16 -> ldsm conflict-free). Only THREE
// __syncthreads per tile (was 16). Next tile's half0 prefetch overlaps the
// second compute half + epilogue.
// ---------------------------------------------------------------------------
#define A_KC 18432             /* per-kc A block: 128 rows * 144B */
#define B_BASE 147456          /* 8 * A_KC */
#define QBK 9216               /* per-kc B block: 192 rows * 48B */
#define QB_D2 4608
#define G_SMEM 221184          /* B_BASE + 8*QBK */

__device__ __forceinline__ void gru_fill_half(uint32_t sb, int t, int n0, int kc0)
{
    int row = t >> 1, seg = t & 1;
    int n = min(n0 + row, N_DST - 1);
    #pragma unroll
    for (int k = 0; k < 4; ++k) {
        int kc = kc0 + k;
        size_t ao = (size_t)n * D + kc * 32 + seg * 16;
        uint32_t so = sb + (uint32_t)(kc * A_KC + row * 144 + seg * 16);
        cp16(so + 0,  g_last_q1 + ao);
        cp16(so + 32, g_last_q2 + ao);
        cp16(so + 64, g_h0_q1 + ao);
        cp16(so + 96, g_h0_q2 + ao);
    }
}

__global__ __launch_bounds__(256, 1) void gru_mma_kernel(
    const float* __restrict__ bih, const float* __restrict__ bhh)
{
    extern __shared__ char sm[];
    uint32_t sb = smem_u32(sm);
    int t = threadIdx.x, lane = t & 31, wid = t >> 5;
    int warp_m = wid & 3, warp_n = wid >> 2;   // 4 x 2
    int bid = blockIdx.x;                       // 0..147
    int c = bid & 15;
    int slot = bid >> 4;                        // 0..9
    int nslots = (c < 4) ? 10 : 9;
    int d0 = c * 16;

    // ---- prologue: resident B (72 KB) + first tile's A half0 ----
    #pragma unroll
    for (int i = 0; i < 12; ++i) {
        int idx = t + i * 256;                 // 0..3071
        int kc = idx / 384, rem = idx % 384;
        int row = rem >> 1, seg = rem & 1;
        cp16(sb + B_BASE + kc * QBK + row * 48 + seg * 16,
             w_gru_q12 + ((size_t)(c * 8 + kc) * 192 + row) * 32 + seg * 16);
    }
    gru_fill_half(sb, t, slot * 128, 0);
    CP_COMMIT();                               // group: B + half0(tile0)

    // ldsm lane offsets
    int arow = lane & 15, aseg = lane >> 4;
    uint32_t aoff = (uint32_t)((warp_m * 32 + arow) * 144 + aseg * 16);
    int bmx = lane >> 3, brow = lane & 7;
    uint32_t boff = (uint32_t)((warp_n * 48 + (bmx >> 1) * 8 + brow) * 48 +
                               (bmx & 1) * 16);
    int lane4 = lane >> 2, lc = lane & 3;

    // ---- hoisted per-thread constants ----
    int dim = d0 + warp_n * 8 + lc * 2;
    float2 birv = *(const float2*)&bih[dim];
    float2 bizv = *(const float2*)&bih[256 + dim];
    float2 binv = *(const float2*)&bih[512 + dim];
    float2 bhrv = *(const float2*)&bhh[dim];
    float2 bhzv = *(const float2*)&bhh[256 + dim];
    float2 bhnv = *(const float2*)&bhh[512 + dim];
    float2 ws0 = *(const float2*)&w_sg[0 * 256 + dim];
    float2 ws1 = *(const float2*)&w_sg[1 * 256 + dim];
    float2 ws2 = *(const float2*)&w_sg[2 * 256 + dim];
    float2 ws3 = *(const float2*)&w_sg[3 * 256 + dim];
    float2 ws4 = *(const float2*)&w_sg[4 * 256 + dim];
    float2 ws5 = *(const float2*)&w_sg[5 * 256 + dim];

    for (int tile = slot; tile < 391; tile += nslots) {
        int n0 = tile * 128;

        int acc1[2][6][4], acc2[2][6][4];
        #pragma unroll
        for (int a = 0; a < 2; ++a)
            #pragma unroll
            for (int b = 0; b < 6; ++b)
                #pragma unroll
                for (int cc = 0; cc < 4; ++cc) { acc1[a][b][cc] = 0; acc2[a][b][cc] = 0; }

        // issue A half1 for this tile
        gru_fill_half(sb, t, n0, 4);
        CP_COMMIT();
        CP_WAIT(1);          // half0 (+B on first iter) landed
        __syncthreads();

        // ---- compute halves: no intra-half syncs ----
        #pragma unroll 1
        for (int half = 0; half < 2; ++half) {
            if (half == 1) {
                CP_WAIT(0);      // half1 landed
                __syncthreads(); // also: all warps done reading half0
                if (tile + nslots < 391) {   // prefetch next tile's half0
                    gru_fill_half(sb, t, (tile + nslots) * 128, 0);
                    CP_COMMIT();
                }
            }
            #pragma unroll
            for (int k = 0; k < 4; ++k) {
                int kc = half * 4 + k;
                uint32_t abase = sb + (uint32_t)(kc * A_KC);
                uint32_t aL1[2][4], aL2[2][4], aH1[2][4], aH2[2][4];
                #pragma unroll
                for (int mt = 0; mt < 2; ++mt) {
                    uint32_t o = aoff + (uint32_t)(mt * 2304);
                    ldsm4(aL1[mt], abase + 0  + o);
                    ldsm4(aL2[mt], abase + 32 + o);
                    ldsm4(aH1[mt], abase + 64 + o);
                    ldsm4(aH2[mt], abase + 96 + o);
                }
                uint32_t kb = sb + B_BASE + (uint32_t)(kc * QBK);
                #pragma unroll
                for (int t8p = 0; t8p < 6; t8p += 2) {
                    uint32_t b1[4], b2[4];
                    uint32_t o = boff + (uint32_t)(t8p * 384);
                    ldsm4(b1, kb + o);              // digit 0 (q1)
                    ldsm4(b2, kb + QB_D2 + o);      // digit 1 (q2)
                    #pragma unroll
                    for (int h = 0; h < 2; ++h) {
                        int t8 = t8p + h;           // == gate index
                        bool useL = (t8 < 3);       // ih gates use 'last'
                        #pragma unroll
                        for (int mt = 0; mt < 2; ++mt) {
                            const uint32_t* q1a = useL ? aL1[mt] : aH1[mt];
                            const uint32_t* q2a = useL ? aL2[mt] : aH2[mt];
                            imma16832(acc1[mt][t8], q1a, b1 + 2 * h);
                            imma16832(acc2[mt][t8], q1a, b2 + 2 * h);
                            imma16832(acc2[mt][t8], q2a, b1 + 2 * h);
                        }
                    }
                }
            }
        }

        // ---- epilogue: 6 gates register-local; rank-1 scales ----
        #pragma unroll
        for (int mt = 0; mt < 2; ++mt) {
            #pragma unroll
            for (int rs = 0; rs < 2; ++rs) {
                int m = n0 + warp_m * 32 + mt * 16 + rs * 8 + lane4;
                if (m < N_DST) {
                    float sl = g_sl[m], sh = g_sh[m];
                    float2 h0v = *(const float2*)&g_h0[(size_t)m * D + dim];
                    float o[2];
                    #pragma unroll
                    for (int e = 0; e < 2; ++e) {
                        int ci = rs * 2 + e;
#define COMB(g, A1, A2) ((float)A1[mt][g][ci] + (float)A2[mt][g][ci] * 0.0078125f)
                        float ir = COMB(0, acc1, acc2) * (sl * (e ? ws0.y : ws0.x)) + (e ? birv.y : birv.x);
                        float iz = COMB(1, acc1, acc2) * (sl * (e ? ws1.y : ws1.x)) + (e ? bizv.y : bizv.x);
                        float in_ = COMB(2, acc1, acc2) * (sl * (e ? ws2.y : ws2.x)) + (e ? binv.y : binv.x);
                        float hr = COMB(3, acc1, acc2) * (sh * (e ? ws3.y : ws3.x)) + (e ? bhrv.y : bhrv.x);
                        float hz = COMB(4, acc1, acc2) * (sh * (e ? ws4.y : ws4.x)) + (e ? bhzv.y : bhzv.x);
                        float hn = COMB(5, acc1, acc2) * (sh * (e ? ws5.y : ws5.x)) + (e ? bhnv.y : bhnv.x);
#undef COMB
                        float r = sigm(ir + hr);
                        float z = sigm(iz + hz);
                        float nn = tanh_f(in_ + r * hn);
                        float h0e = e ? h0v.y : h0v.x;
                        o[e] = (1.f - z) * nn + z * h0e;
                    }
                    *(float2*)&g_h1[(size_t)m * D + dim] = make_float2(o[0], o[1]);
                }
            }
        }
        __syncthreads();   // all warps done reading half1 before next iter refills it
    }
}

// ---------------------------------------------------------------------------
// Kernel 3: LayerNorm + degree-1 bypass; emits split bf16 ft for FC.
// ---------------------------------------------------------------------------
__global__ void ln_kernel(const int* __restrict__ degrees,
                          const float* __restrict__ gamma,
                          const float* __restrict__ beta)
{
    int gw   = (blockIdx.x * blockDim.x + threadIdx.x) >> 5;
    int lane = threadIdx.x & 31;
    if (gw >= N_DST) return;

    int deg = degrees[gw];
    size_t rowo = (size_t)gw * D;
    int base = lane * 8;

    float4 a = *(float4*)&g_h1[rowo + base];
    float4 b = *(float4*)&g_h1[rowo + base + 4];
    float s = a.x + a.y + a.z + a.w + b.x + b.y + b.z + b.w;
    float q = a.x*a.x + a.y*a.y + a.z*a.z + a.w*a.w
            + b.x*b.x + b.y*b.y + b.z*b.z + b.w*b.w;
    #pragma unroll
    for (int o = 16; o > 0; o >>= 1) {
        s += __shfl_xor_sync(0xffffffffu, s, o);
        q += __shfl_xor_sync(0xffffffffu, q, o);
    }
    float mu  = s * (1.f / 256.f);
    float var = q * (1.f / 256.f) - mu * mu;
    float inv = rsqrtf(fmaxf(var, 0.f) + 1e-5f);

    float4 o0, o1;
    if (deg == 1) {
        o0 = *(float4*)&g_last[rowo + base];
        o1 = *(float4*)&g_last[rowo + base + 4];
    } else {
        float4 g0 = *(const float4*)&gamma[base];
        float4 g1 = *(const float4*)&gamma[base + 4];
        float4 e0 = *(const float4*)&beta[base];
        float4 e1 = *(const float4*)&beta[base + 4];
        o0.x = (a.x - mu) * inv * g0.x + e0.x;
        o0.y = (a.y - mu) * inv * g0.y + e0.y;
        o0.z = (a.z - mu) * inv * g0.z + e0.z;
        o0.w = (a.w - mu) * inv * g0.w + e0.w;
        o1.x = (b.x - mu) * inv * g1.x + e1.x;
        o1.y = (b.y - mu) * inv * g1.y + e1.y;
        o1.z = (b.z - mu) * inv * g1.z + e1.z;
        o1.w = (b.w - mu) * inv * g1.w + e1.w;
    }
    split_store8(&g_ft_h[rowo + base], &g_ft_l[rowo + base], o0, o1);
}

// ---------------------------------------------------------------------------
// Kernel 4: FC head, bf16-split mma.sync (unchanged).
// ---------------------------------------------------------------------------
#define F_B_H 20480
#define F_B_L 28800
#define FB_STRIDE 37120
#define F_SMEM (2 * FB_STRIDE)

__device__ __forceinline__ void fc_fill(uint32_t sbuf, int t, int n0, int kc)
{
    int row = t >> 2, seg = t & 3;
    int n = min(n0 + row, N_DST - 1);
    size_t ao = (size_t)n * D + kc * 32 + seg * 8;
    uint32_t so = (uint32_t)(row * 80 + seg * 16);
    cp16(sbuf + 0     + so, g_ft_h + ao);
    cp16(sbuf + 10240 + so, g_ft_l + ao);
    {
        int idx = t;
        int region = (idx >= 416);
        int rem = idx - region * 416;
        int brw = rem >> 2, bsg = rem & 3;
        const __nv_bfloat16* s = (region ? w_fc_l : w_fc_h) +
                                 (size_t)(kc * 104 + brw) * 32 + bsg * 8;
        cp16(sbuf + F_B_H + region * 8320 + brw * 80 + bsg * 16, s);
    }
    if (t < 320) {
        int idx = 512 + t;
        int rem = idx - 416;
        int brw = rem >> 2, bsg = rem & 3;
        const __nv_bfloat16* s = w_fc_l + (size_t)(kc * 104 + brw) * 32 + bsg * 8;
        cp16(sbuf + F_B_H + 8320 + brw * 80 + bsg * 16, s);
    }
}

__global__ __launch_bounds__(512, 1) void fc_mma_kernel(
    const float* __restrict__ fcb, float* __restrict__ out)
{
    extern __shared__ char sm[];
    uint32_t sb = smem_u32(sm);
    int t = threadIdx.x, lane = t & 31, wid = t >> 5;
    int warp_m = wid & 3, warp_n = wid >> 2;   // 4 x 4
    int n0 = blockIdx.x * 128;
    int nt = warp_n ? 3 : 4;
    int t8base = warp_n ? (4 + 3 * (warp_n - 1)) : 0;

    float acc[2][4][4];
    #pragma unroll
    for (int a = 0; a < 2; ++a)
        #pragma unroll
        for (int b = 0; b < 4; ++b)
            #pragma unroll
            for (int cc = 0; cc < 4; ++cc) acc[a][b][cc] = 0.f;

    int alr = ((lane >> 3) & 1) * 8 + (lane & 7);
    int alk = ((lane >> 4) & 1) * 8;
    uint32_t aoff = (uint32_t)((warp_m * 32 + alr) * 80 + alk * 2);
    int l2 = lane & 15;
    uint32_t boff = (uint32_t)((t8base * 8 + (l2 & 7)) * 80 + ((l2 >> 3) * 8) * 2);

    fc_fill(sb, t, n0, 0);
    CP_COMMIT();

    for (int kc = 0; kc < 8; ++kc) {
        uint32_t sbc = sb + (uint32_t)((kc & 1) * FB_STRIDE);
        if (kc < 7) {
            fc_fill(sb + (uint32_t)(((kc + 1) & 1) * FB_STRIDE), t, n0, kc + 1);
            CP_COMMIT();
            CP_WAIT(1);
        } else {
            CP_WAIT(0);
        }
        __syncthreads();

        #pragma unroll
        for (int ks = 0; ks < 2; ++ks) {
            uint32_t aH[2][4], aL[2][4];
            #pragma unroll
            for (int mt = 0; mt < 2; ++mt) {
                uint32_t o = aoff + (uint32_t)(mt * 1280 + ks * 32);
                ldsm4(aH[mt], sbc + 0     + o);
                ldsm4(aL[mt], sbc + 10240 + o);
            }
            #pragma unroll
            for (int t8 = 0; t8 < 4; ++t8) {
                if (t8 < nt) {
                    uint32_t bh[2], bl[2];
                    uint32_t o = boff + (uint32_t)(t8 * 640 + ks * 32);
                    ldsm2(bh, sbc + F_B_H + o);
                    ldsm2(bl, sbc + F_B_L + o);
                    #pragma unroll
                    for (int mt = 0; mt < 2; ++mt) {
                        mma16816(acc[mt][t8], aH[mt], bh);
                        mma16816(acc[mt][t8], aH[mt], bl);
                        mma16816(acc[mt][t8], aL[mt], bh);
                    }
                }
            }
        }
        __syncthreads();
    }

    int lane4 = lane >> 2, lc = lane & 3;
    for (int t8 = 0; t8 < nt; ++t8) {
        int col = (t8base + t8) * 8 + lc * 2;
        float2 bv = *(const float2*)&fcb[col];
        #pragma unroll
        for (int mt = 0; mt < 2; ++mt) {
            #pragma unroll
            for (int rs = 0; rs < 2; ++rs) {
                int m = n0 + warp_m * 32 + mt * 16 + rs * 8 + lane4;
                if (m < N_DST) {
                    float2 o = make_float2(acc[mt][t8][rs * 2 + 0] + bv.x,
                                           acc[mt][t8][rs * 2 + 1] + bv.y);
                    *(float2*)&out[(size_t)m * N_CLS + col] = o;
                }
            }
        }
    }
}

// ---------------------------------------------------------------------------
extern "C" void kernel_launch(void* const* d_in, const int* in_sizes, int n_in,
                              void* d_out, int out_size)
{
    const int*   tokens  = (const int*)  d_in[0];
    const int*   degrees = (const int*)  d_in[1];
    const float* emb     = (const float*)d_in[2];
    const float* W_ih    = (const float*)d_in[3];
    const float* W_hh    = (const float*)d_in[4];
    const float* b_ih    = (const float*)d_in[5];
    const float* b_hh    = (const float*)d_in[6];
    const float* gamma   = (const float*)d_in[7];
    const float* beta    = (const float*)d_in[8];
    const float* fc_w    = (const float*)d_in[9];
    const float* fc_b    = (const float*)d_in[10];
    float* out = (float*)d_out;

    cudaFuncSetAttribute(gru_mma_kernel, cudaFuncAttributeMaxDynamicSharedMemorySize, G_SMEM);
    cudaFuncSetAttribute(fc_mma_kernel,  cudaFuncAttributeMaxDynamicSharedMemorySize, F_SMEM);

    split_w_gru_q<<<192, 256>>>(W_ih, W_hh);
    split_w_fc_kernel<<<(WF_TOTAL + 255) / 256, 256>>>(fc_w);
    gather_kernel<<<(N_DST + 7) / 8, 256>>>(tokens, degrees, emb);
    gru_mma_kernel<<<148, 256, G_SMEM>>>(b_ih, b_hh);
    ln_kernel<<<(N_DST + 7) / 8, 256>>>(degrees, gamma, beta);
    fc_mma_kernel<<<391, 512, F_SMEM>>>(fc_b, out);
}

// round 15
// speedup vs baseline: 1.1765x; 1.1765x over previous
#include <cuda_runtime.h>
#include <cuda_bf16.h>
#include <cstdint>
#include <math.h>

#define N_DST 50000
#define L_MAX 16
#define D 256
#define N_CLS 104

// ---------------------------------------------------------------------------
// Scratch (allocation-free rule: __device__ globals)
// ---------------------------------------------------------------------------
__device__ __align__(16) float g_last[(size_t)N_DST * D];
__device__ __align__(16) float g_h0[(size_t)N_DST * D];
__device__ __align__(16) float g_h1[(size_t)N_DST * D];
// int8 two-digit quantized GEMM operands (A side)
__device__ __align__(16) int8_t g_last_q1[(size_t)N_DST * D];
__device__ __align__(16) int8_t g_last_q2[(size_t)N_DST * D];
__device__ __align__(16) int8_t g_h0_q1[(size_t)N_DST * D];
__device__ __align__(16) int8_t g_h0_q2[(size_t)N_DST * D];
__device__ float g_sl[N_DST];
__device__ float g_sh[N_DST];
// GRU weights, quantized+permuted: [c(8)][kc(8)][digit(2)*192 rows][32]
// row within chunk: row = s*96 + gate*16 + dd
#define WGQ_TOTAL (8 * 8 * 384 * 32)
__device__ __align__(16) int8_t w_gru_q12[WGQ_TOTAL];
__device__ float w_sg[6 * 256];
// FC path stays bf16-split
__device__ __align__(16) __nv_bfloat16 g_ft_h[(size_t)N_DST * D];
__device__ __align__(16) __nv_bfloat16 g_ft_l[(size_t)N_DST * D];
#define WF_TOTAL (8 * 104 * 32)
__device__ __align__(16) __nv_bfloat16 w_fc_h[WF_TOTAL];
__device__ __align__(16) __nv_bfloat16 w_fc_l[WF_TOTAL];

// ---------------------------------------------------------------------------
// Helpers
// ---------------------------------------------------------------------------
__device__ __forceinline__ uint32_t smem_u32(const void* p) {
    uint32_t a;
    asm("{ .reg .u64 t; cvta.to.shared.u64 t, %1; cvt.u32.u64 %0, t; }"
        : "=r"(a) : "l"(p));
    return a;
}
__device__ __forceinline__ void ldsm4(uint32_t* r, uint32_t addr) {
    asm volatile("ldmatrix.sync.aligned.m8n8.x4.shared.b16 {%0,%1,%2,%3}, [%4];"
                 : "=r"(r[0]), "=r"(r[1]), "=r"(r[2]), "=r"(r[3]) : "r"(addr));
}
__device__ __forceinline__ void ldsm2(uint32_t* r, uint32_t addr) {
    asm volatile("ldmatrix.sync.aligned.m8n8.x2.shared.b16 {%0,%1}, [%2];"
                 : "=r"(r[0]), "=r"(r[1]) : "r"(addr));
}
__device__ __forceinline__ void mma16816(float* acc, const uint32_t* a, const uint32_t* b) {
    asm volatile("mma.sync.aligned.m16n8k16.row.col.f32.bf16.bf16.f32 "
                 "{%0,%1,%2,%3}, {%4,%5,%6,%7}, {%8,%9}, {%0,%1,%2,%3};"
                 : "+f"(acc[0]), "+f"(acc[1]), "+f"(acc[2]), "+f"(acc[3])
                 : "r"(a[0]), "r"(a[1]), "r"(a[2]), "r"(a[3]),
                   "r"(b[0]), "r"(b[1]));
}
__device__ __forceinline__ void imma16832(int* d, const uint32_t* a, const uint32_t* b) {
    asm volatile("mma.sync.aligned.m16n8k32.row.col.s32.s8.s8.s32 "
                 "{%0,%1,%2,%3}, {%4,%5,%6,%7}, {%8,%9}, {%0,%1,%2,%3};"
                 : "+r"(d[0]), "+r"(d[1]), "+r"(d[2]), "+r"(d[3])
                 : "r"(a[0]), "r"(a[1]), "r"(a[2]), "r"(a[3]),
                   "r"(b[0]), "r"(b[1]));
}
__device__ __forceinline__ uint32_t pack_bf16(float a, float b) {
    uint32_t r;
    asm("cvt.rn.bf16x2.f32 %0, %1, %2;" : "=r"(r) : "f"(b), "f"(a));
    return r;
}
__device__ __forceinline__ float lowf(uint32_t p) {
    __nv_bfloat162 v = *(__nv_bfloat162*)&p; return __bfloat162float(v.x);
}
__device__ __forceinline__ float highf(uint32_t p) {
    __nv_bfloat162 v = *(__nv_bfloat162*)&p; return __bfloat162float(v.y);
}
__device__ __forceinline__ void split4(float4 v, uint2& hi, uint2& lo) {
    uint32_t h0 = pack_bf16(v.x, v.y);
    uint32_t h1 = pack_bf16(v.z, v.w);
    uint32_t l0 = pack_bf16(v.x - lowf(h0), v.y - highf(h0));
    uint32_t l1 = pack_bf16(v.z - lowf(h1), v.w - highf(h1));
    hi = make_uint2(h0, h1);
    lo = make_uint2(l0, l1);
}
__device__ __forceinline__ void split_store8(__nv_bfloat16* ph, __nv_bfloat16* pl,
                                             float4 a, float4 b) {
    uint2 h0, l0, h1, l1;
    split4(a, h0, l0);
    split4(b, h1, l1);
    *(uint4*)ph = make_uint4(h0.x, h0.y, h1.x, h1.y);
    *(uint4*)pl = make_uint4(l0.x, l0.y, l1.x, l1.y);
}
__device__ __forceinline__ void cp16(uint32_t dst, const void* src) {
    asm volatile("cp.async.cg.shared.global [%0], [%1], 16;"
                 :: "r"(dst), "l"(src));
}
#define CP_COMMIT() asm volatile("cp.async.commit_group;" ::: "memory")
#define CP_WAIT(N)  asm volatile("cp.async.wait_group %0;" :: "n"(N) : "memory")

__device__ __forceinline__ float sigm(float x)   { return 1.f / (1.f + __expf(-x)); }
__device__ __forceinline__ float tanh_f(float x) { return 2.f / (1.f + __expf(-2.f * x)) - 1.f; }

// two-digit int8 quantization of 8 values; inv = 127/max, s1 = max/127
__device__ __forceinline__ void quant8(const float* v, float inv, float s1,
                                       uint2& o1, uint2& o2) {
    uint32_t w1[2] = {0, 0}, w2[2] = {0, 0};
    #pragma unroll
    for (int i = 0; i < 8; ++i) {
        float qf = fminf(fmaxf(rintf(v[i] * inv), -127.f), 127.f);
        float r  = v[i] - qf * s1;
        float q2f = fminf(fmaxf(rintf(r * inv * 128.f), -127.f), 127.f);
        int q1 = (int)qf, q2 = (int)q2f;
        w1[i >> 2] |= ((uint32_t)(q1 & 255)) << ((i & 3) * 8);
        w2[i >> 2] |= ((uint32_t)(q2 & 255)) << ((i & 3) * 8);
    }
    o1 = make_uint2(w1[0], w1[1]);
    o2 = make_uint2(w2[0], w2[1]);
}

// ---------------------------------------------------------------------------
// Kernel 0a: quantize + permute GRU weights. One warp per (c, row).
// Row layout per 32-dim chunk c: row = s*96 + gate*16 + dd.
// ---------------------------------------------------------------------------
__global__ void split_w_gru_q(const float* __restrict__ Wih,
                              const float* __restrict__ Whh)
{
    int wid = threadIdx.x >> 5, lane = threadIdx.x & 31;
    int w = blockIdx.x * 8 + wid;            // 0..1535
    int c = w / 192, row = w % 192;
    int s = row / 96, rem = row % 96;
    int gate = rem >> 4, dd = rem & 15;
    int dim = c * 32 + s * 16 + dd;
    const float* Wp = (gate < 3) ? Wih : Whh;
    int gg = (gate < 3) ? gate : gate - 3;
    const float* src = Wp + (size_t)(gg * 256 + dim) * D + lane * 8;

    float v[8]; float mx = 0.f;
    #pragma unroll
    for (int i = 0; i < 8; ++i) { v[i] = src[i]; mx = fmaxf(mx, fabsf(v[i])); }
    #pragma unroll
    for (int o = 16; o > 0; o >>= 1) mx = fmaxf(mx, __shfl_xor_sync(0xffffffffu, mx, o));
    mx = fmaxf(mx, 1e-20f);
    float s1 = mx * (1.f / 127.f), inv = 127.f / mx;

    uint2 o1, o2;
    quant8(v, inv, s1, o1, o2);
    int kc = lane >> 2, koff = (lane & 3) * 8;
    size_t base = ((size_t)(c * 8 + kc) * 384 + row) * 32 + koff;
    *(uint2*)&w_gru_q12[base]            = o1;   // digit 0 rows [0,192)
    *(uint2*)&w_gru_q12[base + 192 * 32] = o2;   // digit 1 rows [192,384)
    if (lane == 0) w_sg[gate * 256 + dim] = s1;
}

// ---------------------------------------------------------------------------
// Kernel 0b: split fc_w (bf16 hi/lo).
// ---------------------------------------------------------------------------
__global__ void split_w_fc_kernel(const float* __restrict__ fcw)
{
    int idx = blockIdx.x * 256 + threadIdx.x;
    if (idx >= WF_TOTAL) return;
    int k   = idx & 31;
    int r2  = idx >> 5;
    int row = r2 % 104;
    int kc  = r2 / 104;
    float v = fcw[(size_t)row * D + kc * 32 + k];
    __nv_bfloat16 h = __float2bfloat16_rn(v);
    w_fc_h[idx] = h;
    w_fc_l[idx] = __float2bfloat16_rn(v - __bfloat162float(h));
}

// ---------------------------------------------------------------------------
// Kernel 1: mailbox gather. One warp per node; emits fp32 + int8 quantized.
// ---------------------------------------------------------------------------
__global__ void gather_kernel(const int* __restrict__ tokens,
                              const int* __restrict__ degrees,
                              const float* __restrict__ emb)
{
    int gw   = (blockIdx.x * blockDim.x + threadIdx.x) >> 5;
    int lane = threadIdx.x & 31;
    if (gw >= N_DST) return;

    int deg = degrees[gw];
    deg = max(1, min(deg, L_MAX));

    const int* tk = tokens + gw * L_MAX;
    int mytok = (lane < L_MAX) ? tk[lane] : 0;

    int base = lane * 8;
    float4 a0 = make_float4(0.f, 0.f, 0.f, 0.f), a1 = a0;

    for (int l = 0; l < deg - 1; ++l) {
        int tkn = __shfl_sync(0xffffffffu, mytok, l);
        const float4* e = (const float4*)(emb + (size_t)tkn * D + base);
        float4 v0 = e[0], v1 = e[1];
        a0.x += v0.x; a0.y += v0.y; a0.z += v0.z; a0.w += v0.w;
        a1.x += v1.x; a1.y += v1.y; a1.z += v1.z; a1.w += v1.w;
    }
    int tl = __shfl_sync(0xffffffffu, mytok, deg - 1);
    const float4* e = (const float4*)(emb + (size_t)tl * D + base);
    float4 l0 = e[0], l1 = e[1];

    size_t o = (size_t)gw * D + base;
    *(float4*)&g_h0[o]       = a0;
    *(float4*)&g_h0[o + 4]   = a1;
    *(float4*)&g_last[o]     = l0;
    *(float4*)&g_last[o + 4] = l1;

    float vl[8] = {l0.x, l0.y, l0.z, l0.w, l1.x, l1.y, l1.z, l1.w};
    float vh[8] = {a0.x, a0.y, a0.z, a0.w, a1.x, a1.y, a1.z, a1.w};
    float ml = 0.f, mh = 0.f;
    #pragma unroll
    for (int i = 0; i < 8; ++i) {
        ml = fmaxf(ml, fabsf(vl[i]));
        mh = fmaxf(mh, fabsf(vh[i]));
    }
    #pragma unroll
    for (int of = 16; of > 0; of >>= 1) {
        ml = fmaxf(ml, __shfl_xor_sync(0xffffffffu, ml, of));
        mh = fmaxf(mh, __shfl_xor_sync(0xffffffffu, mh, of));
    }
    ml = fmaxf(ml, 1e-20f); mh = fmaxf(mh, 1e-20f);
    float s1l = ml * (1.f / 127.f), invl = 127.f / ml;
    float s1h = mh * (1.f / 127.f), invh = 127.f / mh;

    uint2 q1, q2;
    quant8(vl, invl, s1l, q1, q2);
    *(uint2*)&g_last_q1[o] = q1;
    *(uint2*)&g_last_q2[o] = q2;
    quant8(vh, invh, s1h, q1, q2);
    *(uint2*)&g_h0_q1[o] = q1;
    *(uint2*)&g_h0_q2[o] = q2;
    if (lane == 0) { g_sl[gw] = s1l; g_sh[gw] = s1h; }
}

// ---------------------------------------------------------------------------
// Kernel 2: PERSISTENT fused GRU via two-digit int8 IMMA (R11 optimum).
// Grid = 148 (one CTA per SM). CTA pinned to 32-dim chunk c; B resident in
// smem (144 KB). Loop over ~21 node tiles of 128 (C tile 128x192).
// A double-buffered per k-chunk; next tile's chunk-0 prefetch overlaps the
// epilogue.
// ---------------------------------------------------------------------------
#define QB 0
#define QBK 18432              /* per-kc B block: 384 rows * 48B */
#define QA_BASE 147456
#define QA_REG 6144            /* 128 rows * 48B */
#define QA_BUF 24576           /* 4 regions */
#define G_SMEM (QA_BASE + 2 * QA_BUF)   /* 196608 */

__device__ __forceinline__ void gru_fillA(uint32_t sbuf, int t, int n0, int kc)
{
    int row = t >> 1, seg = t & 1;          // 128 rows x 2 segs = 256 slots
    int n = min(n0 + row, N_DST - 1);
    size_t ao = (size_t)n * D + kc * 32 + seg * 16;
    uint32_t so = (uint32_t)(row * 48 + seg * 16);
    cp16(sbuf + 0 * QA_REG + so, g_last_q1 + ao);
    cp16(sbuf + 1 * QA_REG + so, g_last_q2 + ao);
    cp16(sbuf + 2 * QA_REG + so, g_h0_q1 + ao);
    cp16(sbuf + 3 * QA_REG + so, g_h0_q2 + ao);
}

__global__ __launch_bounds__(256, 1) void gru_mma_kernel(
    const float* __restrict__ bih, const float* __restrict__ bhh)
{
    extern __shared__ char sm[];
    uint32_t sb = smem_u32(sm);
    int t = threadIdx.x, lane = t & 31, wid = t >> 5;
    int warp_m = wid & 3, warp_n = wid >> 2;   // 4 x 2
    int bid = blockIdx.x;                       // 0..147
    int c, slot;
    if (bid < 144) { c = bid & 7; slot = bid >> 3; }
    else           { c = bid - 144; slot = 18; }
    int nslots = (c < 4) ? 19 : 18;
    int d0 = c * 32;

    // ---- prologue: resident B (all 8 k-chunks) + first A chunk ----
    #pragma unroll
    for (int i = 0; i < 24; ++i) {
        int idx = t + i * 256;                 // 0..6143
        int kc = idx / 768, rem = idx % 768;
        int row = rem >> 1, seg = rem & 1;
        cp16(sb + QB + kc * QBK + row * 48 + seg * 16,
             w_gru_q12 + ((size_t)(c * 8 + kc) * 384 + row) * 32 + seg * 16);
    }
    gru_fillA(sb + QA_BASE, t, slot * 128, 0);
    CP_COMMIT();

    // ldsm lane offsets
    int arow = lane & 15, aseg = lane >> 4;
    uint32_t aoff = (uint32_t)((warp_m * 32 + arow) * 48 + aseg * 16);
    int bmx = lane >> 3, brow = lane & 7;
    uint32_t boff = (uint32_t)((warp_n * 96 + (bmx >> 1) * 8 + brow) * 48 +
                               (bmx & 1) * 16);
    int lane4 = lane >> 2, lc = lane & 3;

    for (int tile = slot; tile < 391; tile += nslots) {
        int n0 = tile * 128;

        int acc1[2][12][4], acc2[2][12][4];
        #pragma unroll
        for (int a = 0; a < 2; ++a)
            #pragma unroll
            for (int b = 0; b < 12; ++b)
                #pragma unroll
                for (int cc = 0; cc < 4; ++cc) { acc1[a][b][cc] = 0; acc2[a][b][cc] = 0; }

        for (int kc = 0; kc < 8; ++kc) {
            uint32_t abuf = sb + QA_BASE + (uint32_t)((kc & 1) * QA_BUF);
            if (kc < 7) {
                gru_fillA(sb + QA_BASE + (uint32_t)(((kc + 1) & 1) * QA_BUF),
                          t, n0, kc + 1);
                CP_COMMIT();
                CP_WAIT(1);
            } else {
                CP_WAIT(0);
            }
            __syncthreads();

            uint32_t aL1[2][4], aL2[2][4], aH1[2][4], aH2[2][4];
            #pragma unroll
            for (int mt = 0; mt < 2; ++mt) {
                uint32_t o = aoff + (uint32_t)(mt * 768);
                ldsm4(aL1[mt], abuf + 0 * QA_REG + o);
                ldsm4(aL2[mt], abuf + 1 * QA_REG + o);
                ldsm4(aH1[mt], abuf + 2 * QA_REG + o);
                ldsm4(aH2[mt], abuf + 3 * QA_REG + o);
            }
            uint32_t kb = sb + QB + (uint32_t)(kc * QBK);
            #pragma unroll
            for (int t8p = 0; t8p < 12; t8p += 2) {
                uint32_t b1[4], b2[4];
                uint32_t o = boff + (uint32_t)(t8p * 384);
                ldsm4(b1, kb + o);              // digit 0 (q1)
                ldsm4(b2, kb + 9216 + o);       // digit 1 (q2)
                #pragma unroll
                for (int h = 0; h < 2; ++h) {
                    int t8 = t8p + h;
                    bool useL = (t8 < 6);       // ih gates use 'last'
                    #pragma unroll
                    for (int mt = 0; mt < 2; ++mt) {
                        const uint32_t* q1a = useL ? aL1[mt] : aH1[mt];
                        const uint32_t* q2a = useL ? aL2[mt] : aH2[mt];
                        imma16832(acc1[mt][t8], q1a, b1 + 2 * h);
                        imma16832(acc2[mt][t8], q1a, b2 + 2 * h);
                        imma16832(acc2[mt][t8], q2a, b1 + 2 * h);
                    }
                }
            }
            __syncthreads();
        }

        // prefetch next tile's chunk 0 before running the epilogue
        if (tile + nslots < 391) {
            gru_fillA(sb + QA_BASE, t, (tile + nslots) * 128, 0);
            CP_COMMIT();
        }

        // ---- epilogue: all 6 gates register-local; apply rank-1 scales ----
        #pragma unroll
        for (int jh = 0; jh < 2; ++jh) {
            int dim = d0 + warp_n * 16 + jh * 8 + lc * 2;
            float2 birv = *(const float2*)&bih[dim];
            float2 bizv = *(const float2*)&bih[256 + dim];
            float2 binv = *(const float2*)&bih[512 + dim];
            float2 bhrv = *(const float2*)&bhh[dim];
            float2 bhzv = *(const float2*)&bhh[256 + dim];
            float2 bhnv = *(const float2*)&bhh[512 + dim];
            float2 ws0 = *(const float2*)&w_sg[0 * 256 + dim];
            float2 ws1 = *(const float2*)&w_sg[1 * 256 + dim];
            float2 ws2 = *(const float2*)&w_sg[2 * 256 + dim];
            float2 ws3 = *(const float2*)&w_sg[3 * 256 + dim];
            float2 ws4 = *(const float2*)&w_sg[4 * 256 + dim];
            float2 ws5 = *(const float2*)&w_sg[5 * 256 + dim];
            #pragma unroll
            for (int mt = 0; mt < 2; ++mt) {
                #pragma unroll
                for (int rs = 0; rs < 2; ++rs) {
                    int m = n0 + warp_m * 32 + mt * 16 + rs * 8 + lane4;
                    if (m < N_DST) {
                        float sl = g_sl[m], sh = g_sh[m];
                        float2 h0v = *(const float2*)&g_h0[(size_t)m * D + dim];
                        float o[2];
                        #pragma unroll
                        for (int e = 0; e < 2; ++e) {
                            int ci = rs * 2 + e;
#define COMB(g) ((float)acc1[mt][(g) * 2 + jh][ci] + \
                 (float)acc2[mt][(g) * 2 + jh][ci] * 0.0078125f)
                            float ir = COMB(0) * (sl * (e ? ws0.y : ws0.x)) + (e ? birv.y : birv.x);
                            float iz = COMB(1) * (sl * (e ? ws1.y : ws1.x)) + (e ? bizv.y : bizv.x);
                            float in_ = COMB(2) * (sl * (e ? ws2.y : ws2.x)) + (e ? binv.y : binv.x);
                            float hr = COMB(3) * (sh * (e ? ws3.y : ws3.x)) + (e ? bhrv.y : bhrv.x);
                            float hz = COMB(4) * (sh * (e ? ws4.y : ws4.x)) + (e ? bhzv.y : bhzv.x);
                            float hn = COMB(5) * (sh * (e ? ws5.y : ws5.x)) + (e ? bhnv.y : bhnv.x);
#undef COMB
                            float r = sigm(ir + hr);
                            float z = sigm(iz + hz);
                            float nn = tanh_f(in_ + r * hn);
                            float h0e = e ? h0v.y : h0v.x;
                            o[e] = (1.f - z) * nn + z * h0e;
                        }
                        *(float2*)&g_h1[(size_t)m * D + dim] = make_float2(o[0], o[1]);
                    }
                }
            }
        }
    }
}

// ---------------------------------------------------------------------------
// Kernel 3: LayerNorm + degree-1 bypass; emits split bf16 ft for FC.
// ---------------------------------------------------------------------------
__global__ void ln_kernel(const int* __restrict__ degrees,
                          const float* __restrict__ gamma,
                          const float* __restrict__ beta)
{
    int gw   = (blockIdx.x * blockDim.x + threadIdx.x) >> 5;
    int lane = threadIdx.x & 31;
    if (gw >= N_DST) return;

    int deg = degrees[gw];
    size_t rowo = (size_t)gw * D;
    int base = lane * 8;

    float4 a = *(float4*)&g_h1[rowo + base];
    float4 b = *(float4*)&g_h1[rowo + base + 4];
    float s = a.x + a.y + a.z + a.w + b.x + b.y + b.z + b.w;
    float q = a.x*a.x + a.y*a.y + a.z*a.z + a.w*a.w
            + b.x*b.x + b.y*b.y + b.z*b.z + b.w*b.w;
    #pragma unroll
    for (int o = 16; o > 0; o >>= 1) {
        s += __shfl_xor_sync(0xffffffffu, s, o);
        q += __shfl_xor_sync(0xffffffffu, q, o);
    }
    float mu  = s * (1.f / 256.f);
    float var = q * (1.f / 256.f) - mu * mu;
    float inv = rsqrtf(fmaxf(var, 0.f) + 1e-5f);

    float4 o0, o1;
    if (deg == 1) {
        o0 = *(float4*)&g_last[rowo + base];
        o1 = *(float4*)&g_last[rowo + base + 4];
    } else {
        float4 g0 = *(const float4*)&gamma[base];
        float4 g1 = *(const float4*)&gamma[base + 4];
        float4 e0 = *(const float4*)&beta[base];
        float4 e1 = *(const float4*)&beta[base + 4];
        o0.x = (a.x - mu) * inv * g0.x + e0.x;
        o0.y = (a.y - mu) * inv * g0.y + e0.y;
        o0.z = (a.z - mu) * inv * g0.z + e0.z;
        o0.w = (a.w - mu) * inv * g0.w + e0.w;
        o1.x = (b.x - mu) * inv * g1.x + e1.x;
        o1.y = (b.y - mu) * inv * g1.y + e1.y;
        o1.z = (b.z - mu) * inv * g1.z + e1.z;
        o1.w = (b.w - mu) * inv * g1.w + e1.w;
    }
    split_store8(&g_ft_h[rowo + base], &g_ft_l[rowo + base], o0, o1);
}

// ---------------------------------------------------------------------------
// Kernel 4: PERSISTENT FC head, bf16-split mma.sync.
// Grid = 148, 512 threads. B (split fc_w, all 8 k-chunks) resident in smem
// (133 KB); A (ft splits) double-buffered (2x20 KB). Each CTA loops over
// <=3 node tiles of 128. Inner mma core unchanged (warps 4M x 4N,
// 13 n8 tiles split 4/3/3/3).
// ---------------------------------------------------------------------------
#define FB_A_BUF 20480          /* per-buffer A: hi 10240 + lo 10240 */
#define FB_B_BASE 40960         /* after 2 A buffers */
#define FB_BK 16640             /* per-kc B: hi 8320 + lo 8320 */
#define F_SMEM (FB_B_BASE + 8 * FB_BK)   /* 174080 */

__device__ __forceinline__ void fc_fillA(uint32_t sb, int buf, int t, int n0, int kc)
{
    #pragma unroll
    for (int i = 0; i < 2; ++i) {
        int idx = t + i * 512;              // 0..1023
        int region = idx >> 9;
        int rem = idx & 511;
        int row = rem >> 2, seg = rem & 3;
        int n = min(n0 + row, N_DST - 1);
        const __nv_bfloat16* s = (region ? g_ft_l : g_ft_h) +
                                 (size_t)n * D + kc * 32 + seg * 8;
        cp16(sb + (uint32_t)(buf * FB_A_BUF + region * 10240 + row * 80 + seg * 16), s);
    }
}

__global__ __launch_bounds__(512, 1) void fc_mma_kernel(
    const float* __restrict__ fcb, float* __restrict__ out)
{
    extern __shared__ char sm[];
    uint32_t sb = smem_u32(sm);
    int t = threadIdx.x, lane = t & 31, wid = t >> 5;
    int warp_m = wid & 3, warp_n = wid >> 2;   // 4 x 4
    int bid = blockIdx.x;
    int nt = warp_n ? 3 : 4;
    int t8base = warp_n ? (4 + 3 * (warp_n - 1)) : 0;

    // ---- prologue: resident B (8 kc x (hi+lo) x 104 rows) ----
    #pragma unroll
    for (int i = 0; i < 13; ++i) {
        int idx = t + i * 512;               // 0..6655
        if (idx < 6656) {
            int kc = idx / 832, rem = idx % 832;
            int region = (rem >= 416);
            int r2 = rem - region * 416;
            int brw = r2 >> 2, bsg = r2 & 3;
            const __nv_bfloat16* s = (region ? w_fc_l : w_fc_h) +
                                     (size_t)(kc * 104 + brw) * 32 + bsg * 8;
            cp16(sb + (uint32_t)(FB_B_BASE + kc * FB_BK + region * 8320 +
                                 brw * 80 + bsg * 16), s);
        }
    }

    int alr = ((lane >> 3) & 1) * 8 + (lane & 7);
    int alk = ((lane >> 4) & 1) * 8;
    uint32_t aoff = (uint32_t)((warp_m * 32 + alr) * 80 + alk * 2);
    int l2 = lane & 15;
    uint32_t boff = (uint32_t)((t8base * 8 + (l2 & 7)) * 80 + ((l2 >> 3) * 8) * 2);
    int lane4 = lane >> 2, lc = lane & 3;

    for (int tile = bid; tile < 391; tile += 148) {
        int n0 = tile * 128;

        float acc[2][4][4];
        #pragma unroll
        for (int a = 0; a < 2; ++a)
            #pragma unroll
            for (int b = 0; b < 4; ++b)
                #pragma unroll
                for (int cc = 0; cc < 4; ++cc) acc[a][b][cc] = 0.f;

        fc_fillA(sb, 0, t, n0, 0);
        CP_COMMIT();                 // on first tile this group also carries B

        for (int kc = 0; kc < 8; ++kc) {
            uint32_t sbc = sb + (uint32_t)((kc & 1) * FB_A_BUF);
            if (kc < 7) {
                fc_fillA(sb, (kc + 1) & 1, t, n0, kc + 1);
                CP_COMMIT();
                CP_WAIT(1);
            } else {
                CP_WAIT(0);
            }
            __syncthreads();

            uint32_t kb = sb + (uint32_t)(FB_B_BASE + kc * FB_BK);
            #pragma unroll
            for (int ks = 0; ks < 2; ++ks) {
                uint32_t aH[2][4], aL[2][4];
                #pragma unroll
                for (int mt = 0; mt < 2; ++mt) {
                    uint32_t o = aoff + (uint32_t)(mt * 1280 + ks * 32);
                    ldsm4(aH[mt], sbc + 0     + o);
                    ldsm4(aL[mt], sbc + 10240 + o);
                }
                #pragma unroll
                for (int t8 = 0; t8 < 4; ++t8) {
                    if (t8 < nt) {
                        uint32_t bh[2], bl[2];
                        uint32_t o = boff + (uint32_t)(t8 * 640 + ks * 32);
                        ldsm2(bh, kb + 0    + o);
                        ldsm2(bl, kb + 8320 + o);
                        #pragma unroll
                        for (int mt = 0; mt < 2; ++mt) {
                            mma16816(acc[mt][t8], aH[mt], bh);
                            mma16816(acc[mt][t8], aH[mt], bl);
                            mma16816(acc[mt][t8], aL[mt], bh);
                        }
                    }
                }
            }
            __syncthreads();
        }

        // ---- epilogue ----
        for (int t8 = 0; t8 < nt; ++t8) {
            int col = (t8base + t8) * 8 + lc * 2;
            float2 bv = *(const float2*)&fcb[col];
            #pragma unroll
            for (int mt = 0; mt < 2; ++mt) {
                #pragma unroll
                for (int rs = 0; rs < 2; ++rs) {
                    int m = n0 + warp_m * 32 + mt * 16 + rs * 8 + lane4;
                    if (m < N_DST) {
                        float2 o = make_float2(acc[mt][t8][rs * 2 + 0] + bv.x,
                                               acc[mt][t8][rs * 2 + 1] + bv.y);
                        *(float2*)&out[(size_t)m * N_CLS + col] = o;
                    }
                }
            }
        }
    }
}

// ---------------------------------------------------------------------------
extern "C" void kernel_launch(void* const* d_in, const int* in_sizes, int n_in,
                              void* d_out, int out_size)
{
    const int*   tokens  = (const int*)  d_in[0];
    const int*   degrees = (const int*)  d_in[1];
    const float* emb     = (const float*)d_in[2];
    const float* W_ih    = (const float*)d_in[3];
    const float* W_hh    = (const float*)d_in[4];
    const float* b_ih    = (const float*)d_in[5];
    const float* b_hh    = (const float*)d_in[6];
    const float* gamma   = (const float*)d_in[7];
    const float* beta    = (const float*)d_in[8];
    const float* fc_w    = (const float*)d_in[9];
    const float* fc_b    = (const float*)d_in[10];
    float* out = (float*)d_out;

    cudaFuncSetAttribute(gru_mma_kernel, cudaFuncAttributeMaxDynamicSharedMemorySize, G_SMEM);
    cudaFuncSetAttribute(fc_mma_kernel,  cudaFuncAttributeMaxDynamicSharedMemorySize, F_SMEM);

    split_w_gru_q<<<192, 256>>>(W_ih, W_hh);
    split_w_fc_kernel<<<(WF_TOTAL + 255) / 256, 256>>>(fc_w);
    gather_kernel<<<(N_DST + 7) / 8, 256>>>(tokens, degrees, emb);
    gru_mma_kernel<<<148, 256, G_SMEM>>>(b_ih, b_hh);
    ln_kernel<<<(N_DST + 7) / 8, 256>>>(degrees, gamma, beta);
    fc_mma_kernel<<<148, 512, F_SMEM>>>(fc_b, out);
}

// round 16
// speedup vs baseline: 1.3476x; 1.1454x over previous
#include <cuda_runtime.h>
#include <cuda_bf16.h>
#include <cstdint>
#include <math.h>

#define N_DST 50000
#define L_MAX 16
#define D 256
#define N_CLS 104

// ---------------------------------------------------------------------------
// Scratch (allocation-free rule: __device__ globals)
// ---------------------------------------------------------------------------
__device__ __align__(16) float g_last[(size_t)N_DST * D];
__device__ __align__(16) float g_h0[(size_t)N_DST * D];
__device__ __align__(16) float g_h1[(size_t)N_DST * D];
// int8 two-digit quantized GEMM operands (A side)
__device__ __align__(16) int8_t g_last_q1[(size_t)N_DST * D];
__device__ __align__(16) int8_t g_last_q2[(size_t)N_DST * D];
__device__ __align__(16) int8_t g_h0_q1[(size_t)N_DST * D];
__device__ __align__(16) int8_t g_h0_q2[(size_t)N_DST * D];
#define N_PAD 50176
__device__ __align__(16) float g_sl[N_PAD];
__device__ __align__(16) float g_sh[N_PAD];
// GRU weights, quantized+permuted: [c(8)][kc(8)][digit(2)*192 rows][32]
// row within chunk: row = s*96 + gate*16 + dd
#define WGQ_TOTAL (8 * 8 * 384 * 32)
__device__ __align__(16) int8_t w_gru_q12[WGQ_TOTAL];
__device__ float w_sg[6 * 256];
// FC path stays bf16-split
__device__ __align__(16) __nv_bfloat16 g_ft_h[(size_t)N_DST * D];
__device__ __align__(16) __nv_bfloat16 g_ft_l[(size_t)N_DST * D];
#define WF_TOTAL (8 * 104 * 32)
__device__ __align__(16) __nv_bfloat16 w_fc_h[WF_TOTAL];
__device__ __align__(16) __nv_bfloat16 w_fc_l[WF_TOTAL];

// ---------------------------------------------------------------------------
// Helpers
// ---------------------------------------------------------------------------
__device__ __forceinline__ uint32_t smem_u32(const void* p) {
    uint32_t a;
    asm("{ .reg .u64 t; cvta.to.shared.u64 t, %1; cvt.u32.u64 %0, t; }"
        : "=r"(a) : "l"(p));
    return a;
}
__device__ __forceinline__ void ldsm4(uint32_t* r, uint32_t addr) {
    asm volatile("ldmatrix.sync.aligned.m8n8.x4.shared.b16 {%0,%1,%2,%3}, [%4];"
                 : "=r"(r[0]), "=r"(r[1]), "=r"(r[2]), "=r"(r[3]) : "r"(addr));
}
__device__ __forceinline__ void ldsm2(uint32_t* r, uint32_t addr) {
    asm volatile("ldmatrix.sync.aligned.m8n8.x2.shared.b16 {%0,%1}, [%2];"
                 : "=r"(r[0]), "=r"(r[1]) : "r"(addr));
}
__device__ __forceinline__ void mma16816(float* acc, const uint32_t* a, const uint32_t* b) {
    asm volatile("mma.sync.aligned.m16n8k16.row.col.f32.bf16.bf16.f32 "
                 "{%0,%1,%2,%3}, {%4,%5,%6,%7}, {%8,%9}, {%0,%1,%2,%3};"
                 : "+f"(acc[0]), "+f"(acc[1]), "+f"(acc[2]), "+f"(acc[3])
                 : "r"(a[0]), "r"(a[1]), "r"(a[2]), "r"(a[3]),
                   "r"(b[0]), "r"(b[1]));
}
__device__ __forceinline__ void imma16832(int* d, const uint32_t* a, const uint32_t* b) {
    asm volatile("mma.sync.aligned.m16n8k32.row.col.s32.s8.s8.s32 "
                 "{%0,%1,%2,%3}, {%4,%5,%6,%7}, {%8,%9}, {%0,%1,%2,%3};"
                 : "+r"(d[0]), "+r"(d[1]), "+r"(d[2]), "+r"(d[3])
                 : "r"(a[0]), "r"(a[1]), "r"(a[2]), "r"(a[3]),
                   "r"(b[0]), "r"(b[1]));
}
__device__ __forceinline__ uint32_t pack_bf16(float a, float b) {
    uint32_t r;
    asm("cvt.rn.bf16x2.f32 %0, %1, %2;" : "=r"(r) : "f"(b), "f"(a));
    return r;
}
__device__ __forceinline__ float lowf(uint32_t p) {
    __nv_bfloat162 v = *(__nv_bfloat162*)&p; return __bfloat162float(v.x);
}
__device__ __forceinline__ float highf(uint32_t p) {
    __nv_bfloat162 v = *(__nv_bfloat162*)&p; return __bfloat162float(v.y);
}
__device__ __forceinline__ void split4(float4 v, uint2& hi, uint2& lo) {
    uint32_t h0 = pack_bf16(v.x, v.y);
    uint32_t h1 = pack_bf16(v.z, v.w);
    uint32_t l0 = pack_bf16(v.x - lowf(h0), v.y - highf(h0));
    uint32_t l1 = pack_bf16(v.z - lowf(h1), v.w - highf(h1));
    hi = make_uint2(h0, h1);
    lo = make_uint2(l0, l1);
}
__device__ __forceinline__ void split_store8(__nv_bfloat16* ph, __nv_bfloat16* pl,
                                             float4 a, float4 b) {
    uint2 h0, l0, h1, l1;
    split4(a, h0, l0);
    split4(b, h1, l1);
    *(uint4*)ph = make_uint4(h0.x, h0.y, h1.x, h1.y);
    *(uint4*)pl = make_uint4(l0.x, l0.y, l1.x, l1.y);
}
__device__ __forceinline__ void cp16(uint32_t dst, const void* src) {
    asm volatile("cp.async.cg.shared.global [%0], [%1], 16;"
                 :: "r"(dst), "l"(src));
}
#define CP_COMMIT() asm volatile("cp.async.commit_group;" ::: "memory")
#define CP_WAIT(N)  asm volatile("cp.async.wait_group %0;" :: "n"(N) : "memory")

__device__ __forceinline__ float sigm(float x)   { return 1.f / (1.f + __expf(-x)); }
__device__ __forceinline__ float tanh_f(float x) { return 2.f / (1.f + __expf(-2.f * x)) - 1.f; }

// two-digit int8 quantization of 8 values; inv = 127/max, s1 = max/127
__device__ __forceinline__ void quant8(const float* v, float inv, float s1,
                                       uint2& o1, uint2& o2) {
    uint32_t w1[2] = {0, 0}, w2[2] = {0, 0};
    #pragma unroll
    for (int i = 0; i < 8; ++i) {
        float qf = fminf(fmaxf(rintf(v[i] * inv), -127.f), 127.f);
        float r  = v[i] - qf * s1;
        float q2f = fminf(fmaxf(rintf(r * inv * 128.f), -127.f), 127.f);
        int q1 = (int)qf, q2 = (int)q2f;
        w1[i >> 2] |= ((uint32_t)(q1 & 255)) << ((i & 3) * 8);
        w2[i >> 2] |= ((uint32_t)(q2 & 255)) << ((i & 3) * 8);
    }
    o1 = make_uint2(w1[0], w1[1]);
    o2 = make_uint2(w2[0], w2[1]);
}

// ---------------------------------------------------------------------------
// Kernel 0a: quantize + permute GRU weights. One warp per (c, row).
// Row layout per 32-dim chunk c: row = s*96 + gate*16 + dd.
// ---------------------------------------------------------------------------
__global__ void split_w_gru_q(const float* __restrict__ Wih,
                              const float* __restrict__ Whh)
{
    int wid = threadIdx.x >> 5, lane = threadIdx.x & 31;
    int w = blockIdx.x * 8 + wid;            // 0..1535
    int c = w / 192, row = w % 192;
    int s = row / 96, rem = row % 96;
    int gate = rem >> 4, dd = rem & 15;
    int dim = c * 32 + s * 16 + dd;
    const float* Wp = (gate < 3) ? Wih : Whh;
    int gg = (gate < 3) ? gate : gate - 3;
    const float* src = Wp + (size_t)(gg * 256 + dim) * D + lane * 8;

    float v[8]; float mx = 0.f;
    #pragma unroll
    for (int i = 0; i < 8; ++i) { v[i] = src[i]; mx = fmaxf(mx, fabsf(v[i])); }
    #pragma unroll
    for (int o = 16; o > 0; o >>= 1) mx = fmaxf(mx, __shfl_xor_sync(0xffffffffu, mx, o));
    mx = fmaxf(mx, 1e-20f);
    float s1 = mx * (1.f / 127.f), inv = 127.f / mx;

    uint2 o1, o2;
    quant8(v, inv, s1, o1, o2);
    int kc = lane >> 2, koff = (lane & 3) * 8;
    size_t base = ((size_t)(c * 8 + kc) * 384 + row) * 32 + koff;
    *(uint2*)&w_gru_q12[base]            = o1;   // digit 0 rows [0,192)
    *(uint2*)&w_gru_q12[base + 192 * 32] = o2;   // digit 1 rows [192,384)
    if (lane == 0) w_sg[gate * 256 + dim] = s1;
}

// ---------------------------------------------------------------------------
// Kernel 0b: split fc_w (bf16 hi/lo).
// ---------------------------------------------------------------------------
__global__ void split_w_fc_kernel(const float* __restrict__ fcw)
{
    int idx = blockIdx.x * 256 + threadIdx.x;
    if (idx >= WF_TOTAL) return;
    int k   = idx & 31;
    int r2  = idx >> 5;
    int row = r2 % 104;
    int kc  = r2 / 104;
    float v = fcw[(size_t)row * D + kc * 32 + k];
    __nv_bfloat16 h = __float2bfloat16_rn(v);
    w_fc_h[idx] = h;
    w_fc_l[idx] = __float2bfloat16_rn(v - __bfloat162float(h));
}

// ---------------------------------------------------------------------------
// Kernel 1: mailbox gather. One warp per node; emits fp32 + int8 quantized.
// ---------------------------------------------------------------------------
__global__ void gather_kernel(const int* __restrict__ tokens,
                              const int* __restrict__ degrees,
                              const float* __restrict__ emb)
{
    int gw   = (blockIdx.x * blockDim.x + threadIdx.x) >> 5;
    int lane = threadIdx.x & 31;
    if (gw >= N_DST) return;

    int deg = degrees[gw];
    deg = max(1, min(deg, L_MAX));

    const int* tk = tokens + gw * L_MAX;
    int mytok = (lane < L_MAX) ? tk[lane] : 0;

    int base = lane * 8;
    float4 a0 = make_float4(0.f, 0.f, 0.f, 0.f), a1 = a0;

    for (int l = 0; l < deg - 1; ++l) {
        int tkn = __shfl_sync(0xffffffffu, mytok, l);
        const float4* e = (const float4*)(emb + (size_t)tkn * D + base);
        float4 v0 = e[0], v1 = e[1];
        a0.x += v0.x; a0.y += v0.y; a0.z += v0.z; a0.w += v0.w;
        a1.x += v1.x; a1.y += v1.y; a1.z += v1.z; a1.w += v1.w;
    }
    int tl = __shfl_sync(0xffffffffu, mytok, deg - 1);
    const float4* e = (const float4*)(emb + (size_t)tl * D + base);
    float4 l0 = e[0], l1 = e[1];

    size_t o = (size_t)gw * D + base;
    *(float4*)&g_h0[o]       = a0;
    *(float4*)&g_h0[o + 4]   = a1;
    *(float4*)&g_last[o]     = l0;
    *(float4*)&g_last[o + 4] = l1;

    float vl[8] = {l0.x, l0.y, l0.z, l0.w, l1.x, l1.y, l1.z, l1.w};
    float vh[8] = {a0.x, a0.y, a0.z, a0.w, a1.x, a1.y, a1.z, a1.w};
    float ml = 0.f, mh = 0.f;
    #pragma unroll
    for (int i = 0; i < 8; ++i) {
        ml = fmaxf(ml, fabsf(vl[i]));
        mh = fmaxf(mh, fabsf(vh[i]));
    }
    #pragma unroll
    for (int of = 16; of > 0; of >>= 1) {
        ml = fmaxf(ml, __shfl_xor_sync(0xffffffffu, ml, of));
        mh = fmaxf(mh, __shfl_xor_sync(0xffffffffu, mh, of));
    }
    ml = fmaxf(ml, 1e-20f); mh = fmaxf(mh, 1e-20f);
    float s1l = ml * (1.f / 127.f), invl = 127.f / ml;
    float s1h = mh * (1.f / 127.f), invh = 127.f / mh;

    uint2 q1, q2;
    quant8(vl, invl, s1l, q1, q2);
    *(uint2*)&g_last_q1[o] = q1;
    *(uint2*)&g_last_q2[o] = q2;
    quant8(vh, invh, s1h, q1, q2);
    *(uint2*)&g_h0_q1[o] = q1;
    *(uint2*)&g_h0_q2[o] = q2;
    if (lane == 0) { g_sl[gw] = s1l; g_sh[gw] = s1h; }
}

// ---------------------------------------------------------------------------
// Kernel 2: PERSISTENT fused GRU via two-digit int8 IMMA (R11 core) +
// smem-staged epilogue operands (h0 sub-tile, row scales) loaded by cp.async
// during the kc=0 fill, so the epilogue runs on LDS instead of gmem chains.
// Grid = 148; C tile 128x192; B resident (144 KB); A double-buffered.
// ---------------------------------------------------------------------------
#define QB 0
#define QBK 18432              /* per-kc B block: 384 rows * 48B */
#define QA_BASE 147456
#define QA_REG 6144            /* 128 rows * 48B */
#define QA_BUF 24576           /* 4 regions */
#define EPI_H0 (QA_BASE + 2 * QA_BUF)    /* 196608: 128 rows * 144B */
#define EPI_SL (EPI_H0 + 18432)          /* 215040 */
#define EPI_SH (EPI_SL + 512)            /* 215552 */
#define G_SMEM (EPI_SH + 512)            /* 216064 */

__device__ __forceinline__ void gru_fillA(uint32_t sbuf, int t, int n0, int kc)
{
    int row = t >> 1, seg = t & 1;          // 128 rows x 2 segs = 256 slots
    int n = min(n0 + row, N_DST - 1);
    size_t ao = (size_t)n * D + kc * 32 + seg * 16;
    uint32_t so = (uint32_t)(row * 48 + seg * 16);
    cp16(sbuf + 0 * QA_REG + so, g_last_q1 + ao);
    cp16(sbuf + 1 * QA_REG + so, g_last_q2 + ao);
    cp16(sbuf + 2 * QA_REG + so, g_h0_q1 + ao);
    cp16(sbuf + 3 * QA_REG + so, g_h0_q2 + ao);
}

// Stage epilogue operands: h0[128 x 32] fp32 (pitch 144B), sl/sh[128].
__device__ __forceinline__ void gru_fill_epi(uint32_t sb, int t, int n0, int d0)
{
    #pragma unroll
    for (int i = 0; i < 4; ++i) {
        int idx = t + i * 256;              // 0..1023
        int row = idx >> 3, seg = idx & 7;
        int n = min(n0 + row, N_DST - 1);
        cp16(sb + EPI_H0 + row * 144 + seg * 16,
             g_h0 + (size_t)n * D + d0 + seg * 4);
    }
    if (t < 32)      cp16(sb + EPI_SL + t * 16, g_sl + n0 + t * 4);
    else if (t < 64) cp16(sb + EPI_SH + (t - 32) * 16, g_sh + n0 + (t - 32) * 4);
}

__global__ __launch_bounds__(256, 1) void gru_mma_kernel(
    const float* __restrict__ bih, const float* __restrict__ bhh)
{
    extern __shared__ char sm[];
    uint32_t sb = smem_u32(sm);
    int t = threadIdx.x, lane = t & 31, wid = t >> 5;
    int warp_m = wid & 3, warp_n = wid >> 2;   // 4 x 2
    int bid = blockIdx.x;                       // 0..147
    int c, slot;
    if (bid < 144) { c = bid & 7; slot = bid >> 3; }
    else           { c = bid - 144; slot = 18; }
    int nslots = (c < 4) ? 19 : 18;
    int d0 = c * 32;

    // ---- prologue: resident B (all 8 k-chunks) + first A chunk ----
    #pragma unroll
    for (int i = 0; i < 24; ++i) {
        int idx = t + i * 256;                 // 0..6143
        int kc = idx / 768, rem = idx % 768;
        int row = rem >> 1, seg = rem & 1;
        cp16(sb + QB + kc * QBK + row * 48 + seg * 16,
             w_gru_q12 + ((size_t)(c * 8 + kc) * 384 + row) * 32 + seg * 16);
    }
    gru_fillA(sb + QA_BASE, t, slot * 128, 0);
    CP_COMMIT();

    // ldsm lane offsets
    int arow = lane & 15, aseg = lane >> 4;
    uint32_t aoff = (uint32_t)((warp_m * 32 + arow) * 48 + aseg * 16);
    int bmx = lane >> 3, brow = lane & 7;
    uint32_t boff = (uint32_t)((warp_n * 96 + (bmx >> 1) * 8 + brow) * 48 +
                               (bmx & 1) * 16);
    int lane4 = lane >> 2, lc = lane & 3;

    for (int tile = slot; tile < 391; tile += nslots) {
        int n0 = tile * 128;

        int acc1[2][12][4], acc2[2][12][4];
        #pragma unroll
        for (int a = 0; a < 2; ++a)
            #pragma unroll
            for (int b = 0; b < 12; ++b)
                #pragma unroll
                for (int cc = 0; cc < 4; ++cc) { acc1[a][b][cc] = 0; acc2[a][b][cc] = 0; }

        for (int kc = 0; kc < 8; ++kc) {
            uint32_t abuf = sb + QA_BASE + (uint32_t)((kc & 1) * QA_BUF);
            if (kc < 7) {
                gru_fillA(sb + QA_BASE + (uint32_t)(((kc + 1) & 1) * QA_BUF),
                          t, n0, kc + 1);
                if (kc == 0) gru_fill_epi(sb, t, n0, d0);
                CP_COMMIT();
                CP_WAIT(1);
            } else {
                CP_WAIT(0);
            }
            __syncthreads();

            uint32_t aL1[2][4], aL2[2][4], aH1[2][4], aH2[2][4];
            #pragma unroll
            for (int mt = 0; mt < 2; ++mt) {
                uint32_t o = aoff + (uint32_t)(mt * 768);
                ldsm4(aL1[mt], abuf + 0 * QA_REG + o);
                ldsm4(aL2[mt], abuf + 1 * QA_REG + o);
                ldsm4(aH1[mt], abuf + 2 * QA_REG + o);
                ldsm4(aH2[mt], abuf + 3 * QA_REG + o);
            }
            uint32_t kb = sb + QB + (uint32_t)(kc * QBK);
            #pragma unroll
            for (int t8p = 0; t8p < 12; t8p += 2) {
                uint32_t b1[4], b2[4];
                uint32_t o = boff + (uint32_t)(t8p * 384);
                ldsm4(b1, kb + o);              // digit 0 (q1)
                ldsm4(b2, kb + 9216 + o);       // digit 1 (q2)
                #pragma unroll
                for (int h = 0; h < 2; ++h) {
                    int t8 = t8p + h;
                    bool useL = (t8 < 6);       // ih gates use 'last'
                    #pragma unroll
                    for (int mt = 0; mt < 2; ++mt) {
                        const uint32_t* q1a = useL ? aL1[mt] : aH1[mt];
                        const uint32_t* q2a = useL ? aL2[mt] : aH2[mt];
                        imma16832(acc1[mt][t8], q1a, b1 + 2 * h);
                        imma16832(acc2[mt][t8], q1a, b2 + 2 * h);
                        imma16832(acc2[mt][t8], q2a, b1 + 2 * h);
                    }
                }
            }
            __syncthreads();
        }

        // prefetch next tile's chunk 0 before running the epilogue
        if (tile + nslots < 391) {
            gru_fillA(sb + QA_BASE, t, (tile + nslots) * 128, 0);
            CP_COMMIT();
        }

        // ---- epilogue: gates register-local; operands from smem ----
        #pragma unroll
        for (int jh = 0; jh < 2; ++jh) {
            int dml = warp_n * 16 + jh * 8 + lc * 2;   // dim within chunk
            int dim = d0 + dml;
            float2 birv = *(const float2*)&bih[dim];
            float2 bizv = *(const float2*)&bih[256 + dim];
            float2 binv = *(const float2*)&bih[512 + dim];
            float2 bhrv = *(const float2*)&bhh[dim];
            float2 bhzv = *(const float2*)&bhh[256 + dim];
            float2 bhnv = *(const float2*)&bhh[512 + dim];
            float2 ws0 = *(const float2*)&w_sg[0 * 256 + dim];
            float2 ws1 = *(const float2*)&w_sg[1 * 256 + dim];
            float2 ws2 = *(const float2*)&w_sg[2 * 256 + dim];
            float2 ws3 = *(const float2*)&w_sg[3 * 256 + dim];
            float2 ws4 = *(const float2*)&w_sg[4 * 256 + dim];
            float2 ws5 = *(const float2*)&w_sg[5 * 256 + dim];
            #pragma unroll
            for (int mt = 0; mt < 2; ++mt) {
                #pragma unroll
                for (int rs = 0; rs < 2; ++rs) {
                    int ml = warp_m * 32 + mt * 16 + rs * 8 + lane4;
                    int m = n0 + ml;
                    if (m < N_DST) {
                        float sl = *(const float*)(sm + EPI_SL + ml * 4);
                        float sh = *(const float*)(sm + EPI_SH + ml * 4);
                        float2 h0v = *(const float2*)(sm + EPI_H0 + ml * 144 + dml * 4);
                        float o[2];
                        #pragma unroll
                        for (int e = 0; e < 2; ++e) {
                            int ci = rs * 2 + e;
#define COMB(g) ((float)acc1[mt][(g) * 2 + jh][ci] + \
                 (float)acc2[mt][(g) * 2 + jh][ci] * 0.0078125f)
                            float ir = COMB(0) * (sl * (e ? ws0.y : ws0.x)) + (e ? birv.y : birv.x);
                            float iz = COMB(1) * (sl * (e ? ws1.y : ws1.x)) + (e ? bizv.y : bizv.x);
                            float in_ = COMB(2) * (sl * (e ? ws2.y : ws2.x)) + (e ? binv.y : binv.x);
                            float hr = COMB(3) * (sh * (e ? ws3.y : ws3.x)) + (e ? bhrv.y : bhrv.x);
                            float hz = COMB(4) * (sh * (e ? ws4.y : ws4.x)) + (e ? bhzv.y : bhzv.x);
                            float hn = COMB(5) * (sh * (e ? ws5.y : ws5.x)) + (e ? bhnv.y : bhnv.x);
#undef COMB
                            float r = sigm(ir + hr);
                            float z = sigm(iz + hz);
                            float nn = tanh_f(in_ + r * hn);
                            float h0e = e ? h0v.y : h0v.x;
                            o[e] = (1.f - z) * nn + z * h0e;
                        }
                        *(float2*)&g_h1[(size_t)m * D + dim] = make_float2(o[0], o[1]);
                    }
                }
            }
        }
        __syncthreads();   // protect single-buffered EPI region
    }
}

// ---------------------------------------------------------------------------
// Kernel 3: LayerNorm + degree-1 bypass; emits split bf16 ft for FC.
// ---------------------------------------------------------------------------
__global__ void ln_kernel(const int* __restrict__ degrees,
                          const float* __restrict__ gamma,
                          const float* __restrict__ beta)
{
    int gw   = (blockIdx.x * blockDim.x + threadIdx.x) >> 5;
    int lane = threadIdx.x & 31;
    if (gw >= N_DST) return;

    int deg = degrees[gw];
    size_t rowo = (size_t)gw * D;
    int base = lane * 8;

    float4 a = *(float4*)&g_h1[rowo + base];
    float4 b = *(float4*)&g_h1[rowo + base + 4];
    float s = a.x + a.y + a.z + a.w + b.x + b.y + b.z + b.w;
    float q = a.x*a.x + a.y*a.y + a.z*a.z + a.w*a.w
            + b.x*b.x + b.y*b.y + b.z*b.z + b.w*b.w;
    #pragma unroll
    for (int o = 16; o > 0; o >>= 1) {
        s += __shfl_xor_sync(0xffffffffu, s, o);
        q += __shfl_xor_sync(0xffffffffu, q, o);
    }
    float mu  = s * (1.f / 256.f);
    float var = q * (1.f / 256.f) - mu * mu;
    float inv = rsqrtf(fmaxf(var, 0.f) + 1e-5f);

    float4 o0, o1;
    if (deg == 1) {
        o0 = *(float4*)&g_last[rowo + base];
        o1 = *(float4*)&g_last[rowo + base + 4];
    } else {
        float4 g0 = *(const float4*)&gamma[base];
        float4 g1 = *(const float4*)&gamma[base + 4];
        float4 e0 = *(const float4*)&beta[base];
        float4 e1 = *(const float4*)&beta[base + 4];
        o0.x = (a.x - mu) * inv * g0.x + e0.x;
        o0.y = (a.y - mu) * inv * g0.y + e0.y;
        o0.z = (a.z - mu) * inv * g0.z + e0.z;
        o0.w = (a.w - mu) * inv * g0.w + e0.w;
        o1.x = (b.x - mu) * inv * g1.x + e1.x;
        o1.y = (b.y - mu) * inv * g1.y + e1.y;
        o1.z = (b.z - mu) * inv * g1.z + e1.z;
        o1.w = (b.w - mu) * inv * g1.w + e1.w;
    }
    split_store8(&g_ft_h[rowo + base], &g_ft_l[rowo + base], o0, o1);
}

// ---------------------------------------------------------------------------
// Kernel 4: PERSISTENT FC head, bf16-split mma.sync (R15).
// ---------------------------------------------------------------------------
#define FB_A_BUF 20480
#define FB_B_BASE 40960
#define FB_BK 16640
#define F_SMEM (FB_B_BASE + 8 * FB_BK)   /* 174080 */

__device__ __forceinline__ void fc_fillA(uint32_t sb, int buf, int t, int n0, int kc)
{
    #pragma unroll
    for (int i = 0; i < 2; ++i) {
        int idx = t + i * 512;
        int region = idx >> 9;
        int rem = idx & 511;
        int row = rem >> 2, seg = rem & 3;
        int n = min(n0 + row, N_DST - 1);
        const __nv_bfloat16* s = (region ? g_ft_l : g_ft_h) +
                                 (size_t)n * D + kc * 32 + seg * 8;
        cp16(sb + (uint32_t)(buf * FB_A_BUF + region * 10240 + row * 80 + seg * 16), s);
    }
}

__global__ __launch_bounds__(512, 1) void fc_mma_kernel(
    const float* __restrict__ fcb, float* __restrict__ out)
{
    extern __shared__ char sm[];
    uint32_t sb = smem_u32(sm);
    int t = threadIdx.x, lane = t & 31, wid = t >> 5;
    int warp_m = wid & 3, warp_n = wid >> 2;   // 4 x 4
    int bid = blockIdx.x;
    int nt = warp_n ? 3 : 4;
    int t8base = warp_n ? (4 + 3 * (warp_n - 1)) : 0;

    #pragma unroll
    for (int i = 0; i < 13; ++i) {
        int idx = t + i * 512;
        if (idx < 6656) {
            int kc = idx / 832, rem = idx % 832;
            int region = (rem >= 416);
            int r2 = rem - region * 416;
            int brw = r2 >> 2, bsg = r2 & 3;
            const __nv_bfloat16* s = (region ? w_fc_l : w_fc_h) +
                                     (size_t)(kc * 104 + brw) * 32 + bsg * 8;
            cp16(sb + (uint32_t)(FB_B_BASE + kc * FB_BK + region * 8320 +
                                 brw * 80 + bsg * 16), s);
        }
    }

    int alr = ((lane >> 3) & 1) * 8 + (lane & 7);
    int alk = ((lane >> 4) & 1) * 8;
    uint32_t aoff = (uint32_t)((warp_m * 32 + alr) * 80 + alk * 2);
    int l2 = lane & 15;
    uint32_t boff = (uint32_t)((t8base * 8 + (l2 & 7)) * 80 + ((l2 >> 3) * 8) * 2);
    int lane4 = lane >> 2, lc = lane & 3;

    for (int tile = bid; tile < 391; tile += 148) {
        int n0 = tile * 128;

        float acc[2][4][4];
        #pragma unroll
        for (int a = 0; a < 2; ++a)
            #pragma unroll
            for (int b = 0; b < 4; ++b)
                #pragma unroll
                for (int cc = 0; cc < 4; ++cc) acc[a][b][cc] = 0.f;

        fc_fillA(sb, 0, t, n0, 0);
        CP_COMMIT();

        for (int kc = 0; kc < 8; ++kc) {
            uint32_t sbc = sb + (uint32_t)((kc & 1) * FB_A_BUF);
            if (kc < 7) {
                fc_fillA(sb, (kc + 1) & 1, t, n0, kc + 1);
                CP_COMMIT();
                CP_WAIT(1);
            } else {
                CP_WAIT(0);
            }
            __syncthreads();

            uint32_t kb = sb + (uint32_t)(FB_B_BASE + kc * FB_BK);
            #pragma unroll
            for (int ks = 0; ks < 2; ++ks) {
                uint32_t aH[2][4], aL[2][4];
                #pragma unroll
                for (int mt = 0; mt < 2; ++mt) {
                    uint32_t o = aoff + (uint32_t)(mt * 1280 + ks * 32);
                    ldsm4(aH[mt], sbc + 0     + o);
                    ldsm4(aL[mt], sbc + 10240 + o);
                }
                #pragma unroll
                for (int t8 = 0; t8 < 4; ++t8) {
                    if (t8 < nt) {
                        uint32_t bh[2], bl[2];
                        uint32_t o = boff + (uint32_t)(t8 * 640 + ks * 32);
                        ldsm2(bh, kb + 0    + o);
                        ldsm2(bl, kb + 8320 + o);
                        #pragma unroll
                        for (int mt = 0; mt < 2; ++mt) {
                            mma16816(acc[mt][t8], aH[mt], bh);
                            mma16816(acc[mt][t8], aH[mt], bl);
                            mma16816(acc[mt][t8], aL[mt], bh);
                        }
                    }
                }
            }
            __syncthreads();
        }

        for (int t8 = 0; t8 < nt; ++t8) {
            int col = (t8base + t8) * 8 + lc * 2;
            float2 bv = *(const float2*)&fcb[col];
            #pragma unroll
            for (int mt = 0; mt < 2; ++mt) {
                #pragma unroll
                for (int rs = 0; rs < 2; ++rs) {
                    int m = n0 + warp_m * 32 + mt * 16 + rs * 8 + lane4;
                    if (m < N_DST) {
                        float2 o = make_float2(acc[mt][t8][rs * 2 + 0] + bv.x,
                                               acc[mt][t8][rs * 2 + 1] + bv.y);
                        *(float2*)&out[(size_t)m * N_CLS + col] = o;
                    }
                }
            }
        }
    }
}

// ---------------------------------------------------------------------------
extern "C" void kernel_launch(void* const* d_in, const int* in_sizes, int n_in,
                              void* d_out, int out_size)
{
    const int*   tokens  = (const int*)  d_in[0];
    const int*   degrees = (const int*)  d_in[1];
    const float* emb     = (const float*)d_in[2];
    const float* W_ih    = (const float*)d_in[3];
    const float* W_hh    = (const float*)d_in[4];
    const float* b_ih    = (const float*)d_in[5];
    const float* b_hh    = (const float*)d_in[6];
    const float* gamma   = (const float*)d_in[7];
    const float* beta    = (const float*)d_in[8];
    const float* fc_w    = (const float*)d_in[9];
    const float* fc_b    = (const float*)d_in[10];
    float* out = (float*)d_out;

    cudaFuncSetAttribute(gru_mma_kernel, cudaFuncAttributeMaxDynamicSharedMemorySize, G_SMEM);
    cudaFuncSetAttribute(fc_mma_kernel,  cudaFuncAttributeMaxDynamicSharedMemorySize, F_SMEM);

    split_w_gru_q<<<192, 256>>>(W_ih, W_hh);
    split_w_fc_kernel<<<(WF_TOTAL + 255) / 256, 256>>>(fc_w);
    gather_kernel<<<(N_DST + 7) / 8, 256>>>(tokens, degrees, emb);
    gru_mma_kernel<<<148, 256, G_SMEM>>>(b_ih, b_hh);
    ln_kernel<<<(N_DST + 7) / 8, 256>>>(degrees, gamma, beta);
    fc_mma_kernel<<<148, 512, F_SMEM>>>(fc_b, out);
}